// round 5
// baseline (speedup 1.0000x reference)
#include <cuda_runtime.h>
#include <math.h>

// ---------------- problem constants ----------------
#define T_TOK   1024
#define HDIM    1024
#define NEXP    64
#define IDIM    512
#define TOPK    6
#define NGRP    8
#define TKGRP   3
#define CAP     256
#define SCALE_F 2.5f

// ---------------- device scratch (no runtime allocs allowed) ----------------
__device__ float g_act[NEXP * CAP * IDIM];       // 32 MB  routed act (silu*up)
__device__ float g_y[NEXP * CAP * HDIM];         // 64 MB  routed down output per slot
__device__ float g_shact[T_TOK * HDIM];          //  4 MB  shared-expert act
__device__ float g_shared[T_TOK * HDIM];         //  4 MB  shared-expert output
__device__ int   g_cnt[NEXP];
__device__ int   g_slot_tok[NEXP * CAP];         // token index per (expert, slot)
__device__ int   g_slot_of_a[T_TOK * TOPK];      // slot (e*CAP+pos) per assignment, -1 dropped
__device__ float g_topk_w[T_TOK * TOPK];         // normalized routing weights

// ---------------- f32x2 helpers ----------------
__device__ __forceinline__ unsigned long long pk2(float lo, float hi) {
    unsigned long long r;
    asm("mov.b64 %0, {%1, %2};" : "=l"(r) : "f"(lo), "f"(hi));
    return r;
}
__device__ __forceinline__ void ffma2(unsigned long long& d, unsigned long long a, unsigned long long b) {
    asm("fma.rn.f32x2 %0, %1, %2, %0;" : "+l"(d) : "l"(a), "l"(b));
}
__device__ __forceinline__ float2 upk2(unsigned long long v) {
    float lo, hi;
    asm("mov.b64 {%0, %1}, %2;" : "=f"(lo), "=f"(hi) : "l"(v));
    return make_float2(lo, hi);
}

// ---------------- cp.async helpers ----------------
__device__ __forceinline__ unsigned smem_u32(const void* p) {
    return (unsigned)__cvta_generic_to_shared(p);
}
__device__ __forceinline__ void cp16(unsigned s, const void* g) {
    asm volatile("cp.async.cg.shared.global [%0], [%1], 16;\n" :: "r"(s), "l"(g));
}
#define CP_COMMIT() asm volatile("cp.async.commit_group;\n" ::: "memory")
#define CP_WAIT0()  asm volatile("cp.async.wait_group 0;\n" ::: "memory")

// ---------------- zero expert counters ----------------
__global__ void zero_cnt_kernel() {
    int i = threadIdx.x;
    if (i < NEXP) g_cnt[i] = 0;
}

// ---------------- router: logits GEMM + grouped noaux_tc top-k + dispatch ----------------
__global__ void router_kernel(const float* __restrict__ x,
                              const float* __restrict__ gate_w,
                              const float* __restrict__ e_bias) {
    __shared__ float xs[HDIM];
    __shared__ float part[256];
    __shared__ float logits[NEXP];
    const int t = blockIdx.x, tid = threadIdx.x;

    ((float4*)xs)[tid] = ((const float4*)(x + (long long)t * HDIM))[tid];
    __syncthreads();

    const int e = tid & 63, p = tid >> 6;
    float acc = 0.f;
    const int h0 = p * 256;
#pragma unroll 8
    for (int h = h0; h < h0 + 256; ++h)
        acc = fmaf(xs[h], gate_w[h * NEXP + e], acc);
    part[tid] = acc;
    __syncthreads();
    if (tid < 64)
        logits[tid] = part[tid] + part[tid + 64] + part[tid + 128] + part[tid + 192];
    __syncthreads();

    if (tid == 0) {
        float sc[NEXP], s[NEXP];
        for (int i = 0; i < NEXP; ++i) {
            float v = 1.f / (1.f + expf(-logits[i]));   // sigmoid scores
            sc[i] = v;
            s[i]  = v + e_bias[i];                      // bias-corrected selection score
        }
        float gs[NGRP];
        for (int gi = 0; gi < NGRP; ++gi) {
            float m1 = -1e30f, m2 = -1e30f;
            for (int j = 0; j < 8; ++j) {
                float v = s[gi * 8 + j];
                if (v > m1) { m2 = m1; m1 = v; }
                else if (v > m2) m2 = v;
            }
            gs[gi] = m1 + m2;
        }
        bool gpick[NGRP];
        for (int gi = 0; gi < NGRP; ++gi) gpick[gi] = false;
        for (int r = 0; r < TKGRP; ++r) {
            float best = -1e30f; int bi = 0;
            for (int gi = 0; gi < NGRP; ++gi)
                if (!gpick[gi] && gs[gi] > best) { best = gs[gi]; bi = gi; }
            gpick[bi] = true;
        }
        bool epick[NEXP];
        for (int i = 0; i < NEXP; ++i) epick[i] = false;
        int   eidx[TOPK];
        float wv[TOPK];
        float wsum = 0.f;
        for (int r = 0; r < TOPK; ++r) {
            float best = -1e30f; int bi = 0;
            for (int i = 0; i < NEXP; ++i)
                if (gpick[i >> 3] && !epick[i] && s[i] > best) { best = s[i]; bi = i; }
            epick[bi] = true;
            eidx[r] = bi;
            wv[r]  = sc[bi];
            wsum  += sc[bi];
        }
        const float inv = 1.f / wsum;
        for (int r = 0; r < TOPK; ++r) {
            g_topk_w[t * TOPK + r] = wv[r] * inv;
            const int ex = eidx[r];
            const int pos = atomicAdd(&g_cnt[ex], 1);
            if (pos < CAP) {
                g_slot_tok[ex * CAP + pos]  = t;
                g_slot_of_a[t * TOPK + r]   = ex * CAP + pos;
            } else {
                g_slot_of_a[t * TOPK + r]   = -1;
            }
        }
    }
}

// ---------------- 128x128 / 8x8-per-thread grouped SGEMM (f32x2) ----------------
// Block tile: 128 rows x (SILU ? 64 : 128) output cols; B smem tile always 128 cols.
// SILU=true : smem B cols [0,64)=G (gmem col0+), [64,128)=U (gmem col0+pair_off+);
//             epilogue writes silu(g)*u over 64 output cols.
// MODE: 0 direct rows, 1 gather token rows via slot_tok, 2 expert-offset rows.
#define GBM 128
#define GBK 16

enum { MODE_DIRECT = 0, MODE_GATHER = 1, MODE_EXPOFF = 2 };

template <int MODE, bool SILU>
__global__ __launch_bounds__(256, 2)
void sgemm8(const float* __restrict__ A, const float* __restrict__ B,
            float* __restrict__ Cmat,
            int Kdim, int ldA, int ldB, int ldC,
            int pair_off,
            long long strideAe, long long strideBe, long long strideCe,
            int Mfixed) {
    const int e = blockIdx.z;
    int M;
    if (MODE == MODE_DIRECT) {
        M = Mfixed;
    } else {
        int c = g_cnt[e];
        M = (c < CAP) ? c : CAP;
    }
    const int row0 = blockIdx.y * GBM;
    if (row0 >= M) return;
    const int col0 = blockIdx.x * (SILU ? 64 : 128);

    const float* Ae = A + (long long)e * strideAe;
    const float* Be = B + (long long)e * strideBe;
    float*       Ce = Cmat + (long long)e * strideCe;

    __shared__ __align__(16) float As[2][GBK][GBM];
    __shared__ __align__(16) float Bs[2][GBK][128];
    __shared__ int s_toks[GBM];

    const int tid = threadIdx.x;
    const int tx = tid & 15, ty = tid >> 4;        // compute: 16x16 threads, 8x8 tile
    const int ar = tid & 127, ak = (tid >> 7) * 8; // A loader: row, k-offset (0 or 8)
    const int bk = tid >> 4,  bc = (tid & 15) * 8; // B loader: k-row, col base

    if (MODE == MODE_GATHER) {
        if (tid < GBM) {
            int r = row0 + tid;
            if (r >= M) r = M - 1;
            s_toks[tid] = g_slot_tok[e * CAP + r];
        }
    }
    __syncthreads();

    // A gmem row pointer for this thread's loader role
    const float* aptr;
    if (MODE == MODE_GATHER) {
        aptr = Ae + (long long)s_toks[ar] * ldA + ak;
    } else {
        int r = row0 + ar;
        if (MODE == MODE_EXPOFF && r >= M) r = M - 1;
        aptr = Ae + (long long)r * ldA + ak;
    }
    // B gmem pointer (maps smem col bc -> gmem col, honoring G/U halves for SILU)
    int gcol;
    if (SILU) gcol = (bc < 64) ? (col0 + bc) : (col0 + pair_off + bc - 64);
    else      gcol = col0 + bc;
    const float* bptr = Be + (long long)bk * ldB + gcol;

    // ---- prologue: stage 0 ----
    {
        unsigned s0 = smem_u32(&Bs[0][bk][bc]);
        cp16(s0,      bptr);
        cp16(s0 + 16, bptr + 4);
        CP_COMMIT();
        float4 ra0 = *(const float4*)(aptr);
        float4 ra1 = *(const float4*)(aptr + 4);
        As[0][ak + 0][ar] = ra0.x; As[0][ak + 1][ar] = ra0.y;
        As[0][ak + 2][ar] = ra0.z; As[0][ak + 3][ar] = ra0.w;
        As[0][ak + 4][ar] = ra1.x; As[0][ak + 5][ar] = ra1.y;
        As[0][ak + 6][ar] = ra1.z; As[0][ak + 7][ar] = ra1.w;
        CP_WAIT0();
    }
    __syncthreads();

    unsigned long long acc[4][8];
#pragma unroll
    for (int i = 0; i < 4; ++i)
#pragma unroll
        for (int j = 0; j < 8; ++j) acc[i][j] = 0ull;

    const int KT = Kdim >> 4;
    for (int kt = 0; kt < KT; ++kt) {
        const int cur = kt & 1, nxt = cur ^ 1;
        const bool more = (kt + 1 < KT);
        float4 ra0, ra1;
        if (more) {
            // prefetch B(kt+1) straight to smem, A(kt+1) into regs
            unsigned sn = smem_u32(&Bs[nxt][bk][bc]);
            const float* bp = bptr + (long long)(kt + 1) * GBK * ldB;
            cp16(sn,      bp);
            cp16(sn + 16, bp + 4);
            CP_COMMIT();
            ra0 = *(const float4*)(aptr + (kt + 1) * GBK);
            ra1 = *(const float4*)(aptr + (kt + 1) * GBK + 4);
        }

#pragma unroll
        for (int kk = 0; kk < GBK; ++kk) {
            ulonglong2 va = *(const ulonglong2*)&As[cur][kk][ty * 8];
            ulonglong2 vb = *(const ulonglong2*)&As[cur][kk][ty * 8 + 4];
            float4 b0, b1;
            if (SILU) {
                b0 = *(const float4*)&Bs[cur][kk][tx * 4];        // G
                b1 = *(const float4*)&Bs[cur][kk][64 + tx * 4];   // U
            } else {
                b0 = *(const float4*)&Bs[cur][kk][tx * 8];
                b1 = *(const float4*)&Bs[cur][kk][tx * 8 + 4];
            }
            unsigned long long bd0 = pk2(b0.x, b0.x), bd1 = pk2(b0.y, b0.y);
            unsigned long long bd2 = pk2(b0.z, b0.z), bd3 = pk2(b0.w, b0.w);
            unsigned long long bd4 = pk2(b1.x, b1.x), bd5 = pk2(b1.y, b1.y);
            unsigned long long bd6 = pk2(b1.z, b1.z), bd7 = pk2(b1.w, b1.w);
            ffma2(acc[0][0], va.x, bd0); ffma2(acc[0][1], va.x, bd1);
            ffma2(acc[0][2], va.x, bd2); ffma2(acc[0][3], va.x, bd3);
            ffma2(acc[0][4], va.x, bd4); ffma2(acc[0][5], va.x, bd5);
            ffma2(acc[0][6], va.x, bd6); ffma2(acc[0][7], va.x, bd7);
            ffma2(acc[1][0], va.y, bd0); ffma2(acc[1][1], va.y, bd1);
            ffma2(acc[1][2], va.y, bd2); ffma2(acc[1][3], va.y, bd3);
            ffma2(acc[1][4], va.y, bd4); ffma2(acc[1][5], va.y, bd5);
            ffma2(acc[1][6], va.y, bd6); ffma2(acc[1][7], va.y, bd7);
            ffma2(acc[2][0], vb.x, bd0); ffma2(acc[2][1], vb.x, bd1);
            ffma2(acc[2][2], vb.x, bd2); ffma2(acc[2][3], vb.x, bd3);
            ffma2(acc[2][4], vb.x, bd4); ffma2(acc[2][5], vb.x, bd5);
            ffma2(acc[2][6], vb.x, bd6); ffma2(acc[2][7], vb.x, bd7);
            ffma2(acc[3][0], vb.y, bd0); ffma2(acc[3][1], vb.y, bd1);
            ffma2(acc[3][2], vb.y, bd2); ffma2(acc[3][3], vb.y, bd3);
            ffma2(acc[3][4], vb.y, bd4); ffma2(acc[3][5], vb.y, bd5);
            ffma2(acc[3][6], vb.y, bd6); ffma2(acc[3][7], vb.y, bd7);
        }

        if (more) {
            As[nxt][ak + 0][ar] = ra0.x; As[nxt][ak + 1][ar] = ra0.y;
            As[nxt][ak + 2][ar] = ra0.z; As[nxt][ak + 3][ar] = ra0.w;
            As[nxt][ak + 4][ar] = ra1.x; As[nxt][ak + 5][ar] = ra1.y;
            As[nxt][ak + 6][ar] = ra1.z; As[nxt][ak + 7][ar] = ra1.w;
            CP_WAIT0();
        }
        __syncthreads();
    }

    // ---- epilogue ----
    // acc[pi][j]: rows (row0 + ty*8 + 2*pi, +1) in (lo, hi)
#pragma unroll
    for (int pi = 0; pi < 4; ++pi) {
        const int r0 = row0 + ty * 8 + 2 * pi;
        if (SILU) {
            float2 g0 = upk2(acc[pi][0]), g1 = upk2(acc[pi][1]);
            float2 g2 = upk2(acc[pi][2]), g3 = upk2(acc[pi][3]);
            float2 u0 = upk2(acc[pi][4]), u1 = upk2(acc[pi][5]);
            float2 u2 = upk2(acc[pi][6]), u3 = upk2(acc[pi][7]);
            if (r0 < M) {
                float4 o;
                o.x = g0.x / (1.f + expf(-g0.x)) * u0.x;
                o.y = g1.x / (1.f + expf(-g1.x)) * u1.x;
                o.z = g2.x / (1.f + expf(-g2.x)) * u2.x;
                o.w = g3.x / (1.f + expf(-g3.x)) * u3.x;
                *(float4*)(Ce + (long long)r0 * ldC + col0 + tx * 4) = o;
            }
            if (r0 + 1 < M) {
                float4 o;
                o.x = g0.y / (1.f + expf(-g0.y)) * u0.y;
                o.y = g1.y / (1.f + expf(-g1.y)) * u1.y;
                o.z = g2.y / (1.f + expf(-g2.y)) * u2.y;
                o.w = g3.y / (1.f + expf(-g3.y)) * u3.y;
                *(float4*)(Ce + (long long)(r0 + 1) * ldC + col0 + tx * 4) = o;
            }
        } else {
            float2 c0 = upk2(acc[pi][0]), c1 = upk2(acc[pi][1]);
            float2 c2 = upk2(acc[pi][2]), c3 = upk2(acc[pi][3]);
            float2 c4 = upk2(acc[pi][4]), c5 = upk2(acc[pi][5]);
            float2 c6 = upk2(acc[pi][6]), c7 = upk2(acc[pi][7]);
            if (r0 < M) {
                float* crow = Ce + (long long)r0 * ldC + col0 + tx * 8;
                *(float4*)(crow)     = make_float4(c0.x, c1.x, c2.x, c3.x);
                *(float4*)(crow + 4) = make_float4(c4.x, c5.x, c6.x, c7.x);
            }
            if (r0 + 1 < M) {
                float* crow = Ce + (long long)(r0 + 1) * ldC + col0 + tx * 8;
                *(float4*)(crow)     = make_float4(c0.y, c1.y, c2.y, c3.y);
                *(float4*)(crow + 4) = make_float4(c4.y, c5.y, c6.y, c7.y);
            }
        }
    }
}

// ---------------- combine: out = shared + SCALE * sum_k w_k * y[slot_k] ----------------
__global__ void combine_kernel(float* __restrict__ out) {
    const int t = blockIdx.x;
    const int c = threadIdx.x;  // float4 index 0..255
    float4 sh = *(const float4*)(g_shared + (long long)t * HDIM + c * 4);
    float ax = 0.f, ay = 0.f, az = 0.f, aw = 0.f;
#pragma unroll
    for (int k = 0; k < TOPK; ++k) {
        const int slot = g_slot_of_a[t * TOPK + k];
        const float w = g_topk_w[t * TOPK + k];
        if (slot >= 0) {
            float4 v = *(const float4*)(g_y + (long long)slot * HDIM + c * 4);
            ax += w * v.x; ay += w * v.y; az += w * v.z; aw += w * v.w;
        }
    }
    float4 o;
    o.x = sh.x + SCALE_F * ax;
    o.y = sh.y + SCALE_F * ay;
    o.z = sh.z + SCALE_F * az;
    o.w = sh.w + SCALE_F * aw;
    *(float4*)(out + (long long)t * HDIM + c * 4) = o;
}

// ---------------- host launch ----------------
extern "C" void kernel_launch(void* const* d_in, const int* in_sizes, int n_in,
                              void* d_out, int out_size) {
    (void)in_sizes; (void)n_in; (void)out_size;
    const float* x          = (const float*)d_in[0];   // [T,H]
    const float* gate_w     = (const float*)d_in[1];   // [H,E]
    const float* e_bias     = (const float*)d_in[2];   // [E]
    const float* w_gate_up  = (const float*)d_in[3];   // [E,H,2I]
    const float* w_down     = (const float*)d_in[4];   // [E,I,H]
    const float* ws_gate_up = (const float*)d_in[5];   // [H,2048]
    const float* ws_down    = (const float*)d_in[6];   // [1024,H]
    float* out = (float*)d_out;

    float *p_act, *p_y, *p_shact, *p_shared;
    cudaGetSymbolAddress((void**)&p_act,    g_act);
    cudaGetSymbolAddress((void**)&p_y,      g_y);
    cudaGetSymbolAddress((void**)&p_shact,  g_shact);
    cudaGetSymbolAddress((void**)&p_shared, g_shared);

    zero_cnt_kernel<<<1, 64>>>();
    router_kernel<<<T_TOK, 256>>>(x, gate_w, e_bias);

    // routed gate_up + silu*mul : act[e,slot,0:I]  (out cols 64/block)
    sgemm8<MODE_GATHER, true><<<dim3(IDIM / 64, CAP / GBM, NEXP), 256>>>(
        x, w_gate_up, p_act,
        /*K*/ HDIM, /*ldA*/ HDIM, /*ldB*/ 2 * IDIM, /*ldC*/ IDIM,
        /*pair_off*/ IDIM,
        0LL, (long long)HDIM * 2 * IDIM, (long long)CAP * IDIM, 0);

    // routed down : y[e,slot,0:H]  (out cols 128/block)
    sgemm8<MODE_EXPOFF, false><<<dim3(HDIM / 128, CAP / GBM, NEXP), 256>>>(
        p_act, w_down, p_y,
        /*K*/ IDIM, /*ldA*/ IDIM, /*ldB*/ HDIM, /*ldC*/ HDIM,
        /*pair_off*/ 0,
        (long long)CAP * IDIM, (long long)IDIM * HDIM, (long long)CAP * HDIM, 0);

    // shared gate_up + silu*mul : shact[T,1024]
    sgemm8<MODE_DIRECT, true><<<dim3(1024 / 64, T_TOK / GBM, 1), 256>>>(
        x, ws_gate_up, p_shact,
        /*K*/ HDIM, /*ldA*/ HDIM, /*ldB*/ 2048, /*ldC*/ 1024,
        /*pair_off*/ 1024,
        0LL, 0LL, 0LL, T_TOK);

    // shared down : g_shared[T,H]
    sgemm8<MODE_DIRECT, false><<<dim3(HDIM / 128, T_TOK / GBM, 1), 256>>>(
        p_shact, ws_down, p_shared,
        /*K*/ 1024, /*ldA*/ 1024, /*ldB*/ HDIM, /*ldC*/ HDIM,
        /*pair_off*/ 0,
        0LL, 0LL, 0LL, T_TOK);

    combine_kernel<<<T_TOK, 256>>>(out);
}

// round 7
// speedup vs baseline: 1.5256x; 1.5256x over previous
#include <cuda_runtime.h>
#include <math.h>
#include <stdint.h>

// ---------------- problem constants ----------------
#define T_TOK   1024
#define HDIM    1024
#define NEXP    64
#define IDIM    512
#define TOPK    6
#define NGRP    8
#define TKGRP   3
#define CAP     256
#define SCALE_F 2.5f

// ---------------- device scratch ----------------
__device__ float g_act[NEXP * CAP * IDIM];
__device__ float g_y[NEXP * CAP * HDIM];
__device__ float g_shact[T_TOK * HDIM];
__device__ float g_shared[T_TOK * HDIM];
__device__ int   g_cnt[NEXP];
__device__ int   g_slot_tok[NEXP * CAP];
__device__ int   g_slot_of_a[T_TOK * TOPK];
__device__ float g_topk_w[T_TOK * TOPK];

// ---------------- helpers ----------------
__device__ __forceinline__ uint32_t f2tf32(float f) {
    uint32_t r;
    asm("cvt.rn.tf32.f32 %0, %1;" : "=r"(r) : "f"(f));
    return r;
}
__device__ __forceinline__ void mma_tf32(float* c, const uint32_t* a, const uint32_t* b) {
    asm volatile(
        "mma.sync.aligned.m16n8k8.row.col.f32.tf32.tf32.f32 "
        "{%0,%1,%2,%3}, {%4,%5,%6,%7}, {%8,%9}, {%0,%1,%2,%3};"
        : "+f"(c[0]), "+f"(c[1]), "+f"(c[2]), "+f"(c[3])
        : "r"(a[0]), "r"(a[1]), "r"(a[2]), "r"(a[3]), "r"(b[0]), "r"(b[1]));
}
__device__ __forceinline__ uint4 cvt4(float4 v) {
    uint4 t;
    t.x = f2tf32(v.x); t.y = f2tf32(v.y); t.z = f2tf32(v.z); t.w = f2tf32(v.w);
    return t;
}
__device__ __forceinline__ float silu_mul(float g, float u) {
    return g / (1.f + expf(-g)) * u;
}

// ---------------- zero expert counters ----------------
__global__ void zero_cnt_kernel() {
    int i = threadIdx.x;
    if (i < NEXP) g_cnt[i] = 0;
}

// ---------------- router (exact fp32, unchanged) ----------------
__global__ void router_kernel(const float* __restrict__ x,
                              const float* __restrict__ gate_w,
                              const float* __restrict__ e_bias) {
    __shared__ float xs[HDIM];
    __shared__ float part[256];
    __shared__ float logits[NEXP];
    const int t = blockIdx.x, tid = threadIdx.x;

    ((float4*)xs)[tid] = ((const float4*)(x + (long long)t * HDIM))[tid];
    __syncthreads();

    const int e = tid & 63, p = tid >> 6;
    float acc = 0.f;
    const int h0 = p * 256;
#pragma unroll 8
    for (int h = h0; h < h0 + 256; ++h)
        acc = fmaf(xs[h], gate_w[h * NEXP + e], acc);
    part[tid] = acc;
    __syncthreads();
    if (tid < 64)
        logits[tid] = part[tid] + part[tid + 64] + part[tid + 128] + part[tid + 192];
    __syncthreads();

    if (tid == 0) {
        float sc[NEXP], s[NEXP];
        for (int i = 0; i < NEXP; ++i) {
            float v = 1.f / (1.f + expf(-logits[i]));
            sc[i] = v;
            s[i]  = v + e_bias[i];
        }
        float gs[NGRP];
        for (int gi = 0; gi < NGRP; ++gi) {
            float m1 = -1e30f, m2 = -1e30f;
            for (int j = 0; j < 8; ++j) {
                float v = s[gi * 8 + j];
                if (v > m1) { m2 = m1; m1 = v; }
                else if (v > m2) m2 = v;
            }
            gs[gi] = m1 + m2;
        }
        bool gpick[NGRP];
        for (int gi = 0; gi < NGRP; ++gi) gpick[gi] = false;
        for (int r = 0; r < TKGRP; ++r) {
            float best = -1e30f; int bi = 0;
            for (int gi = 0; gi < NGRP; ++gi)
                if (!gpick[gi] && gs[gi] > best) { best = gs[gi]; bi = gi; }
            gpick[bi] = true;
        }
        bool epick[NEXP];
        for (int i = 0; i < NEXP; ++i) epick[i] = false;
        int   eidx[TOPK];
        float wv[TOPK];
        float wsum = 0.f;
        for (int r = 0; r < TOPK; ++r) {
            float best = -1e30f; int bi = 0;
            for (int i = 0; i < NEXP; ++i)
                if (gpick[i >> 3] && !epick[i] && s[i] > best) { best = s[i]; bi = i; }
            epick[bi] = true;
            eidx[r] = bi;
            wv[r]  = sc[bi];
            wsum  += sc[bi];
        }
        const float inv = 1.f / wsum;
        for (int r = 0; r < TOPK; ++r) {
            g_topk_w[t * TOPK + r] = wv[r] * inv;
            const int ex = eidx[r];
            const int pos = atomicAdd(&g_cnt[ex], 1);
            if (pos < CAP) {
                g_slot_tok[ex * CAP + pos] = t;
                g_slot_of_a[t * TOPK + r]  = ex * CAP + pos;
            } else {
                g_slot_of_a[t * TOPK + r]  = -1;
            }
        }
    }
}

// ---------------- tf32 mma.sync grouped GEMM ----------------
// CTA tile: 128 M x 256 B-cols. 8 warps, warp tile 64x64. ktile = 16.
// SILU=true: B cols interleave G/U in 8-col chunks (chunk 2c = G, 2c+1 = U);
//            epilogue writes silu(g)*u over 128 output cols per CTA.
// Smem: A [2][128][20] (pad-20 -> conflict-free frag reads),
//       B [2][16][264] (pad-264 -> conflict-free frag reads).
enum { MODE_DIRECT = 0, MODE_GATHER = 1, MODE_EXPOFF = 2 };

#define ASTR 20
#define BSTR 264
#define ABUF (128 * ASTR)        // 2560 floats / buffer
#define BBUF (16 * BSTR)         // 4224 floats / buffer
#define SMEM_FLOATS (2 * ABUF + 2 * BBUF)
#define SMEM_BYTES  (SMEM_FLOATS * 4 + 512)

template <int MODE, bool SILU>
__global__ __launch_bounds__(256, 1)
void mgemm(const float* __restrict__ A, const float* __restrict__ B,
           float* __restrict__ Cmat,
           int Kdim, int ldA, int ldB, int ldC, int pair_off,
           long long sAe, long long sBe, long long sCe, int Mfixed) {
    extern __shared__ float sm[];
    float* As = sm;                       // [2][128][ASTR]
    float* Bs = sm + 2 * ABUF;            // [2][16][BSTR]
    int*   s_toks = (int*)(sm + SMEM_FLOATS);

    const int e = blockIdx.z;
    int M;
    if (MODE == MODE_DIRECT) M = Mfixed;
    else { int c = g_cnt[e]; M = (c < CAP) ? c : CAP; }
    const int row0 = blockIdx.y * 128;
    if (row0 >= M) return;
    const int colB0 = blockIdx.x * 256;               // first B col (non-SILU)
    const int colO0 = blockIdx.x * (SILU ? 128 : 256);// first output col

    const float* Ae = A + (long long)e * sAe;
    const float* Be = B + (long long)e * sBe;
    float*       Ce = Cmat + (long long)e * sCe;

    const int tid = threadIdx.x, lane = tid & 31;
    const int w = tid >> 5, wm = w & 1, wn = w >> 1;  // warp 2x4 grid
    const int cl = lane & 3, l2 = lane >> 2;

    // ---- gather table ----
    if (MODE == MODE_GATHER) {
        if (tid < 128) {
            int r = row0 + tid;
            if (r >= M) r = M - 1;
            s_toks[tid] = g_slot_tok[e * CAP + r];
        }
        __syncthreads();
    }

    // ---- A loader: row ar = tid>>1, k-quads {akh*4, akh*4+8} ----
    const int ar = tid >> 1, akh = tid & 1;
    const float* aptr;
    {
        int r = row0 + ar;
        if (MODE != MODE_DIRECT && r >= M) r = M - 1;
        long long grow = (MODE == MODE_GATHER) ? (long long)s_toks[ar] : (long long)r;
        aptr = Ae + grow * ldA + akh * 4;
    }
    float* asts = As + ar * ASTR + akh * 4;  // + buf*ABUF

    // ---- B loader: k-row bk = tid>>4, n-quads {bnq*4 + it*64} ----
    const int bk = tid >> 4, bnq = tid & 15;
    const float* bptr[4];
    float* bsts[4];
#pragma unroll
    for (int it = 0; it < 4; ++it) {
        int n = bnq * 4 + it * 64;           // smem col
        int gcol;
        if (SILU) {
            int pc = n >> 4, lo = n & 15;
            gcol = (lo < 8) ? (colO0 + pc * 8 + lo) : (colO0 + pair_off + pc * 8 + lo - 8);
        } else {
            gcol = colB0 + n;
        }
        bptr[it] = Be + (long long)bk * ldB + gcol;
        bsts[it] = Bs + bk * BSTR + n;       // + buf*BBUF
    }

    // ---- accumulators ----
    float C[4][8][4];
#pragma unroll
    for (int mi = 0; mi < 4; ++mi)
#pragma unroll
        for (int ni = 0; ni < 8; ++ni)
#pragma unroll
            for (int q = 0; q < 4; ++q) C[mi][ni][q] = 0.f;

    const int rbase = wm * 64 + l2;
    const int nbase = wn * 64 + l2;

    // ---- prologue: ktile 0 -> buf 0 ----
    {
        uint4 a0 = cvt4(*(const float4*)(aptr));
        uint4 a1 = cvt4(*(const float4*)(aptr + 8));
        uint4 bv[4];
#pragma unroll
        for (int it = 0; it < 4; ++it) bv[it] = cvt4(*(const float4*)(bptr[it]));
        *(uint4*)(asts)     = a0;
        *(uint4*)(asts + 8) = a1;
#pragma unroll
        for (int it = 0; it < 4; ++it) *(uint4*)(bsts[it]) = bv[it];
    }
    __syncthreads();

    const int KT = Kdim >> 4;
    for (int kt = 0; kt < KT; ++kt) {
        const int cur = kt & 1;
        const bool more = (kt + 1 < KT);
        uint4 pa0, pa1, pb[4];
        if (more) {
            const float* ap = aptr + (kt + 1) * 16;
            pa0 = cvt4(*(const float4*)(ap));
            pa1 = cvt4(*(const float4*)(ap + 8));
            const long long boff = (long long)(kt + 1) * 16 * ldB;
#pragma unroll
            for (int it = 0; it < 4; ++it)
                pb[it] = cvt4(*(const float4*)(bptr[it] + boff));
        }

        const float* Ab = As + cur * ABUF;
        const float* Bb = Bs + cur * BBUF;
#pragma unroll
        for (int ks = 0; ks < 2; ++ks) {
            uint32_t afr[4][4];
#pragma unroll
            for (int mi = 0; mi < 4; ++mi) {
                const float* ap = Ab + (rbase + mi * 16) * ASTR + ks * 8 + cl;
                afr[mi][0] = __float_as_uint(ap[0]);
                afr[mi][1] = __float_as_uint(ap[8 * ASTR]);
                afr[mi][2] = __float_as_uint(ap[4]);
                afr[mi][3] = __float_as_uint(ap[8 * ASTR + 4]);
            }
            uint32_t bfr[8][2];
#pragma unroll
            for (int ni = 0; ni < 8; ++ni) {
                const float* bp = Bb + (ks * 8 + cl) * BSTR + nbase + ni * 8;
                bfr[ni][0] = __float_as_uint(bp[0]);
                bfr[ni][1] = __float_as_uint(bp[4 * BSTR]);
            }
#pragma unroll
            for (int mi = 0; mi < 4; ++mi)
#pragma unroll
                for (int ni = 0; ni < 8; ++ni)
                    mma_tf32(C[mi][ni], afr[mi], bfr[ni]);
        }

        if (more) {
            const int nx = cur ^ 1;
            *(uint4*)(asts + nx * ABUF)     = pa0;
            *(uint4*)(asts + nx * ABUF + 8) = pa1;
#pragma unroll
            for (int it = 0; it < 4; ++it) *(uint4*)(bsts[it] + nx * BBUF) = pb[it];
        }
        __syncthreads();
    }

    // ---- epilogue ----
#pragma unroll
    for (int mi = 0; mi < 4; ++mi) {
        const int r0 = row0 + wm * 64 + mi * 16 + l2;
        const int r1 = r0 + 8;
        const bool ok0 = (MODE == MODE_DIRECT) || (r0 < M);
        const bool ok1 = (MODE == MODE_DIRECT) || (r1 < M);
        if (SILU) {
#pragma unroll
            for (int q = 0; q < 4; ++q) {
                const float* Cg = C[mi][2 * q];
                const float* Cu = C[mi][2 * q + 1];
                const int oc = colO0 + wn * 32 + q * 8 + 2 * cl;
                if (ok0) {
                    float2 o = make_float2(silu_mul(Cg[0], Cu[0]), silu_mul(Cg[1], Cu[1]));
                    *(float2*)(Ce + (long long)r0 * ldC + oc) = o;
                }
                if (ok1) {
                    float2 o = make_float2(silu_mul(Cg[2], Cu[2]), silu_mul(Cg[3], Cu[3]));
                    *(float2*)(Ce + (long long)r1 * ldC + oc) = o;
                }
            }
        } else {
#pragma unroll
            for (int ni = 0; ni < 8; ++ni) {
                const float* Cc = C[mi][ni];
                const int oc = colO0 + wn * 64 + ni * 8 + 2 * cl;
                if (ok0) *(float2*)(Ce + (long long)r0 * ldC + oc) = make_float2(Cc[0], Cc[1]);
                if (ok1) *(float2*)(Ce + (long long)r1 * ldC + oc) = make_float2(Cc[2], Cc[3]);
            }
        }
    }
}

// ---------------- combine ----------------
__global__ void combine_kernel(float* __restrict__ out) {
    const int t = blockIdx.x;
    const int c = threadIdx.x;
    float4 sh = *(const float4*)(g_shared + (long long)t * HDIM + c * 4);
    float ax = 0.f, ay = 0.f, az = 0.f, aw = 0.f;
#pragma unroll
    for (int k = 0; k < TOPK; ++k) {
        const int slot = g_slot_of_a[t * TOPK + k];
        const float w = g_topk_w[t * TOPK + k];
        if (slot >= 0) {
            float4 v = *(const float4*)(g_y + (long long)slot * HDIM + c * 4);
            ax += w * v.x; ay += w * v.y; az += w * v.z; aw += w * v.w;
        }
    }
    float4 o;
    o.x = sh.x + SCALE_F * ax;
    o.y = sh.y + SCALE_F * ay;
    o.z = sh.z + SCALE_F * az;
    o.w = sh.w + SCALE_F * aw;
    *(float4*)(out + (long long)t * HDIM + c * 4) = o;
}

// ---------------- host launch ----------------
extern "C" void kernel_launch(void* const* d_in, const int* in_sizes, int n_in,
                              void* d_out, int out_size) {
    (void)in_sizes; (void)n_in; (void)out_size;
    const float* x          = (const float*)d_in[0];
    const float* gate_w     = (const float*)d_in[1];
    const float* e_bias     = (const float*)d_in[2];
    const float* w_gate_up  = (const float*)d_in[3];   // [E,H,2I]
    const float* w_down     = (const float*)d_in[4];   // [E,I,H]
    const float* ws_gate_up = (const float*)d_in[5];   // [H,2048]
    const float* ws_down    = (const float*)d_in[6];   // [1024,H]
    float* out = (float*)d_out;

    float *p_act, *p_y, *p_shact, *p_shared;
    cudaGetSymbolAddress((void**)&p_act,    g_act);
    cudaGetSymbolAddress((void**)&p_y,      g_y);
    cudaGetSymbolAddress((void**)&p_shact,  g_shact);
    cudaGetSymbolAddress((void**)&p_shared, g_shared);

    static bool attr_done = false;
    if (!attr_done) {
        cudaFuncSetAttribute(mgemm<MODE_GATHER, true>,
                             cudaFuncAttributeMaxDynamicSharedMemorySize, SMEM_BYTES);
        cudaFuncSetAttribute(mgemm<MODE_EXPOFF, false>,
                             cudaFuncAttributeMaxDynamicSharedMemorySize, SMEM_BYTES);
        cudaFuncSetAttribute(mgemm<MODE_DIRECT, true>,
                             cudaFuncAttributeMaxDynamicSharedMemorySize, SMEM_BYTES);
        cudaFuncSetAttribute(mgemm<MODE_DIRECT, false>,
                             cudaFuncAttributeMaxDynamicSharedMemorySize, SMEM_BYTES);
        attr_done = true;
    }

    zero_cnt_kernel<<<1, 64>>>();
    router_kernel<<<T_TOK, 256>>>(x, gate_w, e_bias);

    // routed gate_up + silu*mul : act[e, slot, 0:512]   (128 out cols / CTA)
    mgemm<MODE_GATHER, true><<<dim3(IDIM / 128, CAP / 128, NEXP), 256, SMEM_BYTES>>>(
        x, w_gate_up, p_act,
        /*K*/ HDIM, /*ldA*/ HDIM, /*ldB*/ 2 * IDIM, /*ldC*/ IDIM, /*pair*/ IDIM,
        0LL, (long long)HDIM * 2 * IDIM, (long long)CAP * IDIM, 0);

    // routed down : y[e, slot, 0:1024]   (256 out cols / CTA)
    mgemm<MODE_EXPOFF, false><<<dim3(HDIM / 256, CAP / 128, NEXP), 256, SMEM_BYTES>>>(
        p_act, w_down, p_y,
        /*K*/ IDIM, /*ldA*/ IDIM, /*ldB*/ HDIM, /*ldC*/ HDIM, /*pair*/ 0,
        (long long)CAP * IDIM, (long long)IDIM * HDIM, (long long)CAP * HDIM, 0);

    // shared gate_up + silu*mul : shact[1024, 1024]
    mgemm<MODE_DIRECT, true><<<dim3(1024 / 128, T_TOK / 128, 1), 256, SMEM_BYTES>>>(
        x, ws_gate_up, p_shact,
        /*K*/ HDIM, /*ldA*/ HDIM, /*ldB*/ 2048, /*ldC*/ 1024, /*pair*/ 1024,
        0LL, 0LL, 0LL, T_TOK);

    // shared down : g_shared[1024, 1024]
    mgemm<MODE_DIRECT, false><<<dim3(HDIM / 256, T_TOK / 128, 1), 256, SMEM_BYTES>>>(
        p_shact, ws_down, p_shared,
        /*K*/ 1024, /*ldA*/ 1024, /*ldB*/ HDIM, /*ldC*/ HDIM, /*pair*/ 0,
        0LL, 0LL, 0LL, T_TOK);

    combine_kernel<<<T_TOK, 256>>>(out);
}

// round 12
// speedup vs baseline: 2.1275x; 1.3945x over previous
#include <cuda_runtime.h>
#include <math.h>
#include <stdint.h>

// ---------------- problem constants ----------------
#define T_TOK   1024
#define HDIM    1024
#define NEXP    64
#define IDIM    512
#define TOPK    6
#define NGRP    8
#define TKGRP   3
#define CAP     256
#define SCALE_F 2.5f

// ---------------- device scratch ----------------
__device__ float g_act[NEXP * CAP * IDIM];
__device__ float g_y[NEXP * CAP * HDIM];
__device__ float g_shact[T_TOK * HDIM];
__device__ float g_shared[T_TOK * HDIM];
__device__ int   g_cnt[NEXP];
__device__ int   g_slot_tok[NEXP * CAP];
__device__ int   g_slot_of_a[T_TOK * TOPK];
__device__ float g_topk_w[T_TOK * TOPK];

// ---------------- helpers ----------------
__device__ __forceinline__ uint32_t f2tf32(float f) {
    uint32_t r;
    asm("cvt.rn.tf32.f32 %0, %1;" : "=r"(r) : "f"(f));
    return r;
}
__device__ __forceinline__ void mma_tf32(float* c, const uint32_t* a, const uint32_t* b) {
    asm volatile(
        "mma.sync.aligned.m16n8k8.row.col.f32.tf32.tf32.f32 "
        "{%0,%1,%2,%3}, {%4,%5,%6,%7}, {%8,%9}, {%0,%1,%2,%3};"
        : "+f"(c[0]), "+f"(c[1]), "+f"(c[2]), "+f"(c[3])
        : "r"(a[0]), "r"(a[1]), "r"(a[2]), "r"(a[3]), "r"(b[0]), "r"(b[1]));
}
__device__ __forceinline__ float silu_mul(float g, float u) {
    return g / (1.f + expf(-g)) * u;
}
__device__ __forceinline__ uint32_t smem_u32(const void* p) {
    return (uint32_t)__cvta_generic_to_shared(p);
}
__device__ __forceinline__ void cp16(uint32_t s, const void* g) {
    asm volatile("cp.async.cg.shared.global [%0], [%1], 16;\n" :: "r"(s), "l"(g));
}
#define CP_COMMIT() asm volatile("cp.async.commit_group;\n" ::: "memory")
#define CP_WAIT1()  asm volatile("cp.async.wait_group 1;\n" ::: "memory")
#define CP_WAIT0()  asm volatile("cp.async.wait_group 0;\n" ::: "memory")

// ---------------- zero expert counters ----------------
__global__ void zero_cnt_kernel() {
    int i = threadIdx.x;
    if (i < NEXP) g_cnt[i] = 0;
}

// ---------------- router (exact fp32) ----------------
__global__ void router_kernel(const float* __restrict__ x,
                              const float* __restrict__ gate_w,
                              const float* __restrict__ e_bias) {
    __shared__ float xs[HDIM];
    __shared__ float part[256];
    __shared__ float logits[NEXP];
    const int t = blockIdx.x, tid = threadIdx.x;

    ((float4*)xs)[tid] = ((const float4*)(x + (long long)t * HDIM))[tid];
    __syncthreads();

    const int e = tid & 63, p = tid >> 6;
    float acc = 0.f;
    const int h0 = p * 256;
#pragma unroll 8
    for (int h = h0; h < h0 + 256; ++h)
        acc = fmaf(xs[h], gate_w[h * NEXP + e], acc);
    part[tid] = acc;
    __syncthreads();
    if (tid < 64)
        logits[tid] = part[tid] + part[tid + 64] + part[tid + 128] + part[tid + 192];
    __syncthreads();

    if (tid == 0) {
        float sc[NEXP], s[NEXP];
        for (int i = 0; i < NEXP; ++i) {
            float v = 1.f / (1.f + expf(-logits[i]));
            sc[i] = v;
            s[i]  = v + e_bias[i];
        }
        float gs[NGRP];
        for (int gi = 0; gi < NGRP; ++gi) {
            float m1 = -1e30f, m2 = -1e30f;
            for (int j = 0; j < 8; ++j) {
                float v = s[gi * 8 + j];
                if (v > m1) { m2 = m1; m1 = v; }
                else if (v > m2) m2 = v;
            }
            gs[gi] = m1 + m2;
        }
        bool gpick[NGRP];
        for (int gi = 0; gi < NGRP; ++gi) gpick[gi] = false;
        for (int r = 0; r < TKGRP; ++r) {
            float best = -1e30f; int bi = 0;
            for (int gi = 0; gi < NGRP; ++gi)
                if (!gpick[gi] && gs[gi] > best) { best = gs[gi]; bi = gi; }
            gpick[bi] = true;
        }
        bool epick[NEXP];
        for (int i = 0; i < NEXP; ++i) epick[i] = false;
        int   eidx[TOPK];
        float wv[TOPK];
        float wsum = 0.f;
        for (int r = 0; r < TOPK; ++r) {
            float best = -1e30f; int bi = 0;
            for (int i = 0; i < NEXP; ++i)
                if (gpick[i >> 3] && !epick[i] && s[i] > best) { best = s[i]; bi = i; }
            epick[bi] = true;
            eidx[r] = bi;
            wv[r]  = sc[bi];
            wsum  += sc[bi];
        }
        const float inv = 1.f / wsum;
        for (int r = 0; r < TOPK; ++r) {
            g_topk_w[t * TOPK + r] = wv[r] * inv;
            const int ex = eidx[r];
            const int pos = atomicAdd(&g_cnt[ex], 1);
            if (pos < CAP) {
                g_slot_tok[ex * CAP + pos] = t;
                g_slot_of_a[t * TOPK + r]  = ex * CAP + pos;
            } else {
                g_slot_of_a[t * TOPK + r]  = -1;
            }
        }
    }
}

// ---------------- tf32 mma.sync grouped GEMM, 3-stage cp.async ----------------
// CTA tile: 128 M x 256 B-cols, 8 warps (2x4), warp tile 64x64, ktile = 32.
// smem holds raw fp32; cvt.rn.tf32 applied at fragment-read time.
// SILU=true: B cols interleave G/U in 8-col chunks (chunk 2c=G, 2c+1=U);
//            epilogue writes silu(g)*u over 128 output cols per CTA.
enum { MODE_DIRECT = 0, MODE_GATHER = 1, MODE_EXPOFF = 2 };

#define KTILE 32
#define ASTR 36
#define BSTR 264
#define ABUF (128 * ASTR)        // floats per A stage
#define BBUF (KTILE * BSTR)      // floats per B stage
#define NSTG 3
#define SMEM_FLOATS (NSTG * (ABUF + BBUF))
#define SMEM_BYTES  (SMEM_FLOATS * 4 + 512)

template <int MODE, bool SILU>
__global__ __launch_bounds__(256, 1)
void mgemm(const float* __restrict__ A, const float* __restrict__ B,
           float* __restrict__ Cmat,
           int Kdim, int ldA, int ldB, int ldC, int pair_off,
           long long sAe, long long sBe, long long sCe, int Mfixed) {
    extern __shared__ float sm[];
    float* As = sm;                           // [NSTG][128][ASTR]
    float* Bs = sm + NSTG * ABUF;             // [NSTG][KTILE][BSTR]
    int*   s_toks = (int*)(sm + SMEM_FLOATS);

    const int e = blockIdx.z;
    int M;
    if (MODE == MODE_DIRECT) M = Mfixed;
    else { int c = g_cnt[e]; M = (c < CAP) ? c : CAP; }
    const int row0 = blockIdx.y * 128;
    if (row0 >= M) return;
    const int colB0 = blockIdx.x * 256;
    const int colO0 = blockIdx.x * (SILU ? 128 : 256);

    const float* Ae = A + (long long)e * sAe;
    const float* Be = B + (long long)e * sBe;
    float*       Ce = Cmat + (long long)e * sCe;

    const int tid = threadIdx.x, lane = tid & 31;
    const int w = tid >> 5, wm = w & 1, wn = w >> 1;
    const int cl = lane & 3, l2 = lane >> 2;

    if (MODE == MODE_GATHER) {
        if (tid < 128) {
            int r = row0 + tid;
            if (r >= M) r = M - 1;
            s_toks[tid] = g_slot_tok[e * CAP + r];
        }
        __syncthreads();
    }

    // ---- A loader: row ar = tid>>1, 16 consecutive floats at (tid&1)*16 ----
    const int ar = tid >> 1, af0 = (tid & 1) * 16;
    const float* aptr;
    {
        int r = row0 + ar;
        if (MODE != MODE_DIRECT && r >= M) r = M - 1;
        long long grow = (MODE == MODE_GATHER) ? (long long)s_toks[ar] : (long long)r;
        aptr = Ae + grow * ldA + af0;
    }
    const uint32_t a_s0 = smem_u32(As + ar * ASTR + af0);

    // ---- B loader: k-row bk = tid>>3, 32 consecutive smem floats at (tid&7)*32 ----
    const int bk = tid >> 3, bc0 = (tid & 7) * 32;
    const float* bgp[8];
#pragma unroll
    for (int j = 0; j < 8; ++j) {
        int n0 = bc0 + j * 4;
        int gcol;
        if (SILU) {
            int pc = n0 >> 4, lo = n0 & 15;
            gcol = (lo < 8) ? (colO0 + pc * 8 + lo) : (colO0 + pair_off + pc * 8 + lo - 8);
        } else {
            gcol = colB0 + n0;
        }
        bgp[j] = Be + (long long)bk * ldB + gcol;
    }
    const uint32_t b_s0 = smem_u32(Bs + bk * BSTR + bc0);

    auto load_stage = [&](int s, int kt) {
        const long long koff = (long long)kt * KTILE;
        uint32_t sa = a_s0 + s * (ABUF * 4);
        const float* ag = aptr + koff;
        cp16(sa,      ag);
        cp16(sa + 16, ag + 4);
        cp16(sa + 32, ag + 8);
        cp16(sa + 48, ag + 12);
        uint32_t sb = b_s0 + s * (BBUF * 4);
        const long long boff = koff * ldB;
#pragma unroll
        for (int j = 0; j < 8; ++j)
            cp16(sb + j * 16, bgp[j] + boff);
        CP_COMMIT();
    };

    // ---- accumulators ----
    float C[4][8][4];
#pragma unroll
    for (int mi = 0; mi < 4; ++mi)
#pragma unroll
        for (int ni = 0; ni < 8; ++ni)
#pragma unroll
            for (int q = 0; q < 4; ++q) C[mi][ni][q] = 0.f;

    const int rbase = wm * 64 + l2;
    const int nbase = wn * 64 + l2;

    const int KT = Kdim / KTILE;   // >= 2 for all our shapes
    load_stage(0, 0);
    load_stage(1, 1);
    CP_WAIT1();
    __syncthreads();

    int sc = 0;
    for (int kt = 0; kt < KT; ++kt) {
        int sl = sc + 2; if (sl >= NSTG) sl -= NSTG;
        if (kt + 2 < KT) load_stage(sl, kt + 2);

        const float* Ab = As + sc * ABUF;
        const float* Bb = Bs + sc * BBUF;
#pragma unroll
        for (int ks = 0; ks < 4; ++ks) {
            uint32_t afr[4][4];
#pragma unroll
            for (int mi = 0; mi < 4; ++mi) {
                const float* ap = Ab + (rbase + mi * 16) * ASTR + ks * 8 + cl;
                afr[mi][0] = f2tf32(ap[0]);
                afr[mi][1] = f2tf32(ap[8 * ASTR]);
                afr[mi][2] = f2tf32(ap[4]);
                afr[mi][3] = f2tf32(ap[8 * ASTR + 4]);
            }
            uint32_t bfr[8][2];
#pragma unroll
            for (int ni = 0; ni < 8; ++ni) {
                const float* bp = Bb + (ks * 8 + cl) * BSTR + nbase + ni * 8;
                bfr[ni][0] = f2tf32(bp[0]);
                bfr[ni][1] = f2tf32(bp[4 * BSTR]);
            }
#pragma unroll
            for (int mi = 0; mi < 4; ++mi)
#pragma unroll
                for (int ni = 0; ni < 8; ++ni)
                    mma_tf32(C[mi][ni], afr[mi], bfr[ni]);
        }

        if (kt + 1 < KT) {
            if (kt + 2 < KT) { CP_WAIT1(); } else { CP_WAIT0(); }
            __syncthreads();
        }
        sc = (sc + 1 == NSTG) ? 0 : sc + 1;
    }

    // ---- epilogue ----
#pragma unroll
    for (int mi = 0; mi < 4; ++mi) {
        const int r0 = row0 + wm * 64 + mi * 16 + l2;
        const int r1 = r0 + 8;
        const bool ok0 = (MODE == MODE_DIRECT) || (r0 < M);
        const bool ok1 = (MODE == MODE_DIRECT) || (r1 < M);
        if (SILU) {
#pragma unroll
            for (int q = 0; q < 4; ++q) {
                const float* Cg = C[mi][2 * q];
                const float* Cu = C[mi][2 * q + 1];
                const int oc = colO0 + wn * 32 + q * 8 + 2 * cl;
                if (ok0) {
                    float2 o = make_float2(silu_mul(Cg[0], Cu[0]), silu_mul(Cg[1], Cu[1]));
                    *(float2*)(Ce + (long long)r0 * ldC + oc) = o;
                }
                if (ok1) {
                    float2 o = make_float2(silu_mul(Cg[2], Cu[2]), silu_mul(Cg[3], Cu[3]));
                    *(float2*)(Ce + (long long)r1 * ldC + oc) = o;
                }
            }
        } else {
#pragma unroll
            for (int ni = 0; ni < 8; ++ni) {
                const float* Cc = C[mi][ni];
                const int oc = colO0 + wn * 64 + ni * 8 + 2 * cl;
                if (ok0) *(float2*)(Ce + (long long)r0 * ldC + oc) = make_float2(Cc[0], Cc[1]);
                if (ok1) *(float2*)(Ce + (long long)r1 * ldC + oc) = make_float2(Cc[2], Cc[3]);
            }
        }
    }
}

// ---------------- combine ----------------
__global__ void combine_kernel(float* __restrict__ out) {
    const int t = blockIdx.x;
    const int c = threadIdx.x;
    float4 sh = *(const float4*)(g_shared + (long long)t * HDIM + c * 4);
    float ax = 0.f, ay = 0.f, az = 0.f, aw = 0.f;
#pragma unroll
    for (int k = 0; k < TOPK; ++k) {
        const int slot = g_slot_of_a[t * TOPK + k];
        const float w = g_topk_w[t * TOPK + k];
        if (slot >= 0) {
            float4 v = *(const float4*)(g_y + (long long)slot * HDIM + c * 4);
            ax += w * v.x; ay += w * v.y; az += w * v.z; aw += w * v.w;
        }
    }
    float4 o;
    o.x = sh.x + SCALE_F * ax;
    o.y = sh.y + SCALE_F * ay;
    o.z = sh.z + SCALE_F * az;
    o.w = sh.w + SCALE_F * aw;
    *(float4*)(out + (long long)t * HDIM + c * 4) = o;
}

// ---------------- host launch ----------------
extern "C" void kernel_launch(void* const* d_in, const int* in_sizes, int n_in,
                              void* d_out, int out_size) {
    (void)in_sizes; (void)n_in; (void)out_size;
    const float* x          = (const float*)d_in[0];
    const float* gate_w     = (const float*)d_in[1];
    const float* e_bias     = (const float*)d_in[2];
    const float* w_gate_up  = (const float*)d_in[3];   // [E,H,2I]
    const float* w_down     = (const float*)d_in[4];   // [E,I,H]
    const float* ws_gate_up = (const float*)d_in[5];   // [H,2048]
    const float* ws_down    = (const float*)d_in[6];   // [1024,H]
    float* out = (float*)d_out;

    float *p_act, *p_y, *p_shact, *p_shared;
    cudaGetSymbolAddress((void**)&p_act,    g_act);
    cudaGetSymbolAddress((void**)&p_y,      g_y);
    cudaGetSymbolAddress((void**)&p_shact,  g_shact);
    cudaGetSymbolAddress((void**)&p_shared, g_shared);

    static cudaStream_t s2 = nullptr;
    static cudaEvent_t  evA = nullptr, evB = nullptr;
    static bool init_done = false;
    if (!init_done) {
        cudaFuncSetAttribute(mgemm<MODE_GATHER, true>,
                             cudaFuncAttributeMaxDynamicSharedMemorySize, SMEM_BYTES);
        cudaFuncSetAttribute(mgemm<MODE_EXPOFF, false>,
                             cudaFuncAttributeMaxDynamicSharedMemorySize, SMEM_BYTES);
        cudaFuncSetAttribute(mgemm<MODE_DIRECT, true>,
                             cudaFuncAttributeMaxDynamicSharedMemorySize, SMEM_BYTES);
        cudaFuncSetAttribute(mgemm<MODE_DIRECT, false>,
                             cudaFuncAttributeMaxDynamicSharedMemorySize, SMEM_BYTES);
        cudaStreamCreateWithFlags(&s2, cudaStreamNonBlocking);
        cudaEventCreateWithFlags(&evA, cudaEventDisableTiming);
        cudaEventCreateWithFlags(&evB, cudaEventDisableTiming);
        init_done = true;
    }

    zero_cnt_kernel<<<1, 64>>>();
    cudaEventRecord(evA, 0);
    cudaStreamWaitEvent(s2, evA, 0);

    // ---- shared experts on side stream (independent of routing) ----
    mgemm<MODE_DIRECT, true><<<dim3(1024 / 128, T_TOK / 128, 1), 256, SMEM_BYTES, s2>>>(
        x, ws_gate_up, p_shact,
        HDIM, HDIM, 2048, 1024, /*pair*/ 1024,
        0LL, 0LL, 0LL, T_TOK);
    mgemm<MODE_DIRECT, false><<<dim3(HDIM / 256, T_TOK / 128, 1), 256, SMEM_BYTES, s2>>>(
        p_shact, ws_down, p_shared,
        1024, 1024, HDIM, HDIM, /*pair*/ 0,
        0LL, 0LL, 0LL, T_TOK);
    cudaEventRecord(evB, s2);

    // ---- routed path on default stream ----
    router_kernel<<<T_TOK, 256>>>(x, gate_w, e_bias);

    mgemm<MODE_GATHER, true><<<dim3(IDIM / 128, CAP / 128, NEXP), 256, SMEM_BYTES>>>(
        x, w_gate_up, p_act,
        HDIM, HDIM, 2 * IDIM, IDIM, /*pair*/ IDIM,
        0LL, (long long)HDIM * 2 * IDIM, (long long)CAP * IDIM, 0);

    mgemm<MODE_EXPOFF, false><<<dim3(HDIM / 256, CAP / 128, NEXP), 256, SMEM_BYTES>>>(
        p_act, w_down, p_y,
        IDIM, IDIM, HDIM, HDIM, /*pair*/ 0,
        (long long)CAP * IDIM, (long long)IDIM * HDIM, (long long)CAP * HDIM, 0);

    cudaStreamWaitEvent(0, evB, 0);
    combine_kernel<<<T_TOK, 256>>>(out);
}

// round 13
// speedup vs baseline: 2.2881x; 1.0755x over previous
#include <cuda_runtime.h>
#include <math.h>
#include <stdint.h>

// ---------------- problem constants ----------------
#define T_TOK   1024
#define HDIM    1024
#define NEXP    64
#define IDIM    512
#define TOPK    6
#define NGRP    8
#define TKGRP   3
#define CAP     256
#define SCALE_F 2.5f

// ---------------- device scratch ----------------
__device__ float g_act[NEXP * CAP * IDIM];
__device__ float g_y[NEXP * CAP * HDIM];
__device__ float g_shact[T_TOK * HDIM];
__device__ float g_shared[T_TOK * HDIM];
__device__ int   g_cnt[NEXP];
__device__ int   g_slot_tok[NEXP * CAP];
__device__ int   g_slot_of_a[T_TOK * TOPK];
__device__ float g_topk_w[T_TOK * TOPK];

// ---------------- helpers ----------------
__device__ __forceinline__ uint32_t f2tf32(float f) {
    uint32_t r;
    asm("cvt.rn.tf32.f32 %0, %1;" : "=r"(r) : "f"(f));
    return r;
}
__device__ __forceinline__ void mma_tf32(float* c, const uint32_t* a, const uint32_t* b) {
    asm volatile(
        "mma.sync.aligned.m16n8k8.row.col.f32.tf32.tf32.f32 "
        "{%0,%1,%2,%3}, {%4,%5,%6,%7}, {%8,%9}, {%0,%1,%2,%3};"
        : "+f"(c[0]), "+f"(c[1]), "+f"(c[2]), "+f"(c[3])
        : "r"(a[0]), "r"(a[1]), "r"(a[2]), "r"(a[3]), "r"(b[0]), "r"(b[1]));
}
__device__ __forceinline__ float silu_mul(float g, float u) {
    return g / (1.f + expf(-g)) * u;
}
__device__ __forceinline__ uint32_t smem_u32(const void* p) {
    return (uint32_t)__cvta_generic_to_shared(p);
}
__device__ __forceinline__ void cp16(uint32_t s, const void* g) {
    asm volatile("cp.async.cg.shared.global [%0], [%1], 16;\n" :: "r"(s), "l"(g));
}
#define CP_COMMIT() asm volatile("cp.async.commit_group;\n" ::: "memory")
#define CP_WAIT1()  asm volatile("cp.async.wait_group 1;\n" ::: "memory")
#define CP_WAIT0()  asm volatile("cp.async.wait_group 0;\n" ::: "memory")

// ---------------- zero expert counters ----------------
__global__ void zero_cnt_kernel() {
    int i = threadIdx.x;
    if (i < NEXP) g_cnt[i] = 0;
}

// ---------------- warp-per-token router ----------------
// 8 warps/block, warp w handles token t = blockIdx.x*8 + w.
// Lane owns experts e0=2*lane, e1=2*lane+1. Selection is warp-parallel with
// tie-breaking identical to jax top_k (highest value, lowest index on ties).
__global__ __launch_bounds__(256)
void router_kernel(const float* __restrict__ x,
                   const float* __restrict__ gate_w,
                   const float* __restrict__ e_bias) {
    __shared__ float xs[8][HDIM];
    const int tid = threadIdx.x, w = tid >> 5, lane = tid & 31;
    const int t = blockIdx.x * 8 + w;

    // load x row into this warp's smem slice
    {
        const float4* xrow = (const float4*)(x + (long long)t * HDIM);
        float4* dst = (float4*)xs[w];
#pragma unroll
        for (int j = 0; j < 8; ++j)
            dst[lane + j * 32] = xrow[lane + j * 32];
    }
    __syncwarp();

    // logits for e0 = 2*lane, e1 = 2*lane+1 (two chains each to break latency)
    const int e0 = 2 * lane, e1 = e0 + 1;
    float a0a = 0.f, a0b = 0.f, a1a = 0.f, a1b = 0.f;
    const float* gw = gate_w + e0;
#pragma unroll 4
    for (int h = 0; h < HDIM; h += 2) {
        float xv0 = xs[w][h], xv1 = xs[w][h + 1];
        float2 g0 = *(const float2*)(gw + (long long)h * NEXP);
        float2 g1 = *(const float2*)(gw + (long long)(h + 1) * NEXP);
        a0a = fmaf(xv0, g0.x, a0a); a1a = fmaf(xv0, g0.y, a1a);
        a0b = fmaf(xv1, g1.x, a0b); a1b = fmaf(xv1, g1.y, a1b);
    }
    const float logit0 = a0a + a0b, logit1 = a1a + a1b;

    const float sc0 = 1.f / (1.f + expf(-logit0));
    const float sc1 = 1.f / (1.f + expf(-logit1));
    float s0 = sc0 + e_bias[e0];
    float s1 = sc1 + e_bias[e1];

    // ---- group scores: top-2 sum within each group of 8 experts (4 lanes) ----
    float m1 = fmaxf(s0, s1), m2 = fminf(s0, s1);
#pragma unroll
    for (int d = 1; d < 4; d <<= 1) {
        float o1 = __shfl_xor_sync(0xffffffffu, m1, d);
        float o2 = __shfl_xor_sync(0xffffffffu, m2, d);
        float nm1 = fmaxf(m1, o1);
        float nm2 = fmaxf(fminf(m1, o1), fmaxf(m2, o2));
        m1 = nm1; m2 = nm2;
    }
    const float gscore = m1 + m2;     // identical on the 4 lanes of each group

    // gather the 8 group scores (lane 4*gi holds group gi)
    float gs[NGRP];
#pragma unroll
    for (int gi = 0; gi < NGRP; ++gi)
        gs[gi] = __shfl_sync(0xffffffffu, gscore, gi * 4);

    // top-3 groups, computed redundantly on every lane (strict >, lowest idx ties)
    bool gpick[NGRP];
#pragma unroll
    for (int gi = 0; gi < NGRP; ++gi) gpick[gi] = false;
#pragma unroll
    for (int r = 0; r < TKGRP; ++r) {
        float best = -1e30f; int bi = 0;
#pragma unroll
        for (int gi = 0; gi < NGRP; ++gi)
            if (!gpick[gi] && gs[gi] > best) { best = gs[gi]; bi = gi; }
        gpick[bi] = true;
    }
    if (!gpick[e0 >> 3]) s0 = -1e30f;
    if (!gpick[e1 >> 3]) s1 = -1e30f;

    // ---- top-6 experts via 6 warp argmax reductions ----
    float wv[TOPK];
    int   eidx[TOPK];
    float wsum = 0.f;
#pragma unroll
    for (int r = 0; r < TOPK; ++r) {
        float lv; int li;
        if (s0 >= s1) { lv = s0; li = e0; } else { lv = s1; li = e1; }
#pragma unroll
        for (int d = 16; d >= 1; d >>= 1) {
            float ov = __shfl_xor_sync(0xffffffffu, lv, d);
            int   oi = __shfl_xor_sync(0xffffffffu, li, d);
            if (ov > lv || (ov == lv && oi < li)) { lv = ov; li = oi; }
        }
        // li uniform across warp now
        float scv = __shfl_sync(0xffffffffu, (li & 1) ? sc1 : sc0, li >> 1);
        wv[r] = scv; eidx[r] = li; wsum += scv;
        if ((li >> 1) == lane) { if (li & 1) s1 = -1e30f; else s0 = -1e30f; }
    }

    if (lane == 0) {
        const float inv = 1.f / wsum;
#pragma unroll
        for (int r = 0; r < TOPK; ++r) {
            g_topk_w[t * TOPK + r] = wv[r] * inv;
            const int ex = eidx[r];
            const int pos = atomicAdd(&g_cnt[ex], 1);
            if (pos < CAP) {
                g_slot_tok[ex * CAP + pos] = t;
                g_slot_of_a[t * TOPK + r]  = ex * CAP + pos;
            } else {
                g_slot_of_a[t * TOPK + r]  = -1;
            }
        }
    }
}

// ---------------- tf32 mma.sync grouped GEMM, 3-stage cp.async ----------------
// CTA tile: 128 M x 256 B-cols, 8 warps (2x4), warp tile 64x64, ktile = 32.
// smem holds raw fp32; cvt.rn.tf32 applied at fragment-read time.
// SILU=true: B cols interleave G/U in 8-col chunks (chunk 2c=G, 2c+1=U);
//            epilogue writes silu(g)*u over 128 output cols per CTA.
enum { MODE_DIRECT = 0, MODE_GATHER = 1, MODE_EXPOFF = 2 };

#define KTILE 32
#define ASTR 36
#define BSTR 264
#define ABUF (128 * ASTR)
#define BBUF (KTILE * BSTR)
#define NSTG 3
#define SMEM_FLOATS (NSTG * (ABUF + BBUF))
#define SMEM_BYTES  (SMEM_FLOATS * 4 + 512)

template <int MODE, bool SILU>
__global__ __launch_bounds__(256, 1)
void mgemm(const float* __restrict__ A, const float* __restrict__ B,
           float* __restrict__ Cmat,
           int Kdim, int ldA, int ldB, int ldC, int pair_off,
           long long sAe, long long sBe, long long sCe, int Mfixed) {
    extern __shared__ float sm[];
    float* As = sm;
    float* Bs = sm + NSTG * ABUF;
    int*   s_toks = (int*)(sm + SMEM_FLOATS);

    const int e = blockIdx.z;
    int M;
    if (MODE == MODE_DIRECT) M = Mfixed;
    else { int c = g_cnt[e]; M = (c < CAP) ? c : CAP; }
    const int row0 = blockIdx.y * 128;
    if (row0 >= M) return;
    const int colB0 = blockIdx.x * 256;
    const int colO0 = blockIdx.x * (SILU ? 128 : 256);

    const float* Ae = A + (long long)e * sAe;
    const float* Be = B + (long long)e * sBe;
    float*       Ce = Cmat + (long long)e * sCe;

    const int tid = threadIdx.x, lane = tid & 31;
    const int w = tid >> 5, wm = w & 1, wn = w >> 1;
    const int cl = lane & 3, l2 = lane >> 2;

    if (MODE == MODE_GATHER) {
        if (tid < 128) {
            int r = row0 + tid;
            if (r >= M) r = M - 1;
            s_toks[tid] = g_slot_tok[e * CAP + r];
        }
        __syncthreads();
    }

    const int ar = tid >> 1, af0 = (tid & 1) * 16;
    const float* aptr;
    {
        int r = row0 + ar;
        if (MODE != MODE_DIRECT && r >= M) r = M - 1;
        long long grow = (MODE == MODE_GATHER) ? (long long)s_toks[ar] : (long long)r;
        aptr = Ae + grow * ldA + af0;
    }
    const uint32_t a_s0 = smem_u32(As + ar * ASTR + af0);

    const int bk = tid >> 3, bc0 = (tid & 7) * 32;
    const float* bgp[8];
#pragma unroll
    for (int j = 0; j < 8; ++j) {
        int n0 = bc0 + j * 4;
        int gcol;
        if (SILU) {
            int pc = n0 >> 4, lo = n0 & 15;
            gcol = (lo < 8) ? (colO0 + pc * 8 + lo) : (colO0 + pair_off + pc * 8 + lo - 8);
        } else {
            gcol = colB0 + n0;
        }
        bgp[j] = Be + (long long)bk * ldB + gcol;
    }
    const uint32_t b_s0 = smem_u32(Bs + bk * BSTR + bc0);

    auto load_stage = [&](int s, int kt) {
        const long long koff = (long long)kt * KTILE;
        uint32_t sa = a_s0 + s * (ABUF * 4);
        const float* ag = aptr + koff;
        cp16(sa,      ag);
        cp16(sa + 16, ag + 4);
        cp16(sa + 32, ag + 8);
        cp16(sa + 48, ag + 12);
        uint32_t sb = b_s0 + s * (BBUF * 4);
        const long long boff = koff * ldB;
#pragma unroll
        for (int j = 0; j < 8; ++j)
            cp16(sb + j * 16, bgp[j] + boff);
        CP_COMMIT();
    };

    float C[4][8][4];
#pragma unroll
    for (int mi = 0; mi < 4; ++mi)
#pragma unroll
        for (int ni = 0; ni < 8; ++ni)
#pragma unroll
            for (int q = 0; q < 4; ++q) C[mi][ni][q] = 0.f;

    const int rbase = wm * 64 + l2;
    const int nbase = wn * 64 + l2;

    const int KT = Kdim / KTILE;
    load_stage(0, 0);
    load_stage(1, 1);
    CP_WAIT1();
    __syncthreads();

    int sc = 0;
    for (int kt = 0; kt < KT; ++kt) {
        int sl = sc + 2; if (sl >= NSTG) sl -= NSTG;
        if (kt + 2 < KT) load_stage(sl, kt + 2);

        const float* Ab = As + sc * ABUF;
        const float* Bb = Bs + sc * BBUF;
#pragma unroll
        for (int ks = 0; ks < 4; ++ks) {
            uint32_t afr[4][4];
#pragma unroll
            for (int mi = 0; mi < 4; ++mi) {
                const float* ap = Ab + (rbase + mi * 16) * ASTR + ks * 8 + cl;
                afr[mi][0] = f2tf32(ap[0]);
                afr[mi][1] = f2tf32(ap[8 * ASTR]);
                afr[mi][2] = f2tf32(ap[4]);
                afr[mi][3] = f2tf32(ap[8 * ASTR + 4]);
            }
            uint32_t bfr[8][2];
#pragma unroll
            for (int ni = 0; ni < 8; ++ni) {
                const float* bp = Bb + (ks * 8 + cl) * BSTR + nbase + ni * 8;
                bfr[ni][0] = f2tf32(bp[0]);
                bfr[ni][1] = f2tf32(bp[4 * BSTR]);
            }
#pragma unroll
            for (int mi = 0; mi < 4; ++mi)
#pragma unroll
                for (int ni = 0; ni < 8; ++ni)
                    mma_tf32(C[mi][ni], afr[mi], bfr[ni]);
        }

        if (kt + 1 < KT) {
            if (kt + 2 < KT) { CP_WAIT1(); } else { CP_WAIT0(); }
            __syncthreads();
        }
        sc = (sc + 1 == NSTG) ? 0 : sc + 1;
    }

#pragma unroll
    for (int mi = 0; mi < 4; ++mi) {
        const int r0 = row0 + wm * 64 + mi * 16 + l2;
        const int r1 = r0 + 8;
        const bool ok0 = (MODE == MODE_DIRECT) || (r0 < M);
        const bool ok1 = (MODE == MODE_DIRECT) || (r1 < M);
        if (SILU) {
#pragma unroll
            for (int q = 0; q < 4; ++q) {
                const float* Cg = C[mi][2 * q];
                const float* Cu = C[mi][2 * q + 1];
                const int oc = colO0 + wn * 32 + q * 8 + 2 * cl;
                if (ok0) {
                    float2 o = make_float2(silu_mul(Cg[0], Cu[0]), silu_mul(Cg[1], Cu[1]));
                    *(float2*)(Ce + (long long)r0 * ldC + oc) = o;
                }
                if (ok1) {
                    float2 o = make_float2(silu_mul(Cg[2], Cu[2]), silu_mul(Cg[3], Cu[3]));
                    *(float2*)(Ce + (long long)r1 * ldC + oc) = o;
                }
            }
        } else {
#pragma unroll
            for (int ni = 0; ni < 8; ++ni) {
                const float* Cc = C[mi][ni];
                const int oc = colO0 + wn * 64 + ni * 8 + 2 * cl;
                if (ok0) *(float2*)(Ce + (long long)r0 * ldC + oc) = make_float2(Cc[0], Cc[1]);
                if (ok1) *(float2*)(Ce + (long long)r1 * ldC + oc) = make_float2(Cc[2], Cc[3]);
            }
        }
    }
}

// ---------------- combine ----------------
__global__ void combine_kernel(float* __restrict__ out) {
    const int t = blockIdx.x;
    const int c = threadIdx.x;
    float4 sh = *(const float4*)(g_shared + (long long)t * HDIM + c * 4);
    float ax = 0.f, ay = 0.f, az = 0.f, aw = 0.f;
#pragma unroll
    for (int k = 0; k < TOPK; ++k) {
        const int slot = g_slot_of_a[t * TOPK + k];
        const float w = g_topk_w[t * TOPK + k];
        if (slot >= 0) {
            float4 v = *(const float4*)(g_y + (long long)slot * HDIM + c * 4);
            ax += w * v.x; ay += w * v.y; az += w * v.z; aw += w * v.w;
        }
    }
    float4 o;
    o.x = sh.x + SCALE_F * ax;
    o.y = sh.y + SCALE_F * ay;
    o.z = sh.z + SCALE_F * az;
    o.w = sh.w + SCALE_F * aw;
    *(float4*)(out + (long long)t * HDIM + c * 4) = o;
}

// ---------------- host launch ----------------
extern "C" void kernel_launch(void* const* d_in, const int* in_sizes, int n_in,
                              void* d_out, int out_size) {
    (void)in_sizes; (void)n_in; (void)out_size;
    const float* x          = (const float*)d_in[0];
    const float* gate_w     = (const float*)d_in[1];
    const float* e_bias     = (const float*)d_in[2];
    const float* w_gate_up  = (const float*)d_in[3];   // [E,H,2I]
    const float* w_down     = (const float*)d_in[4];   // [E,I,H]
    const float* ws_gate_up = (const float*)d_in[5];   // [H,2048]
    const float* ws_down    = (const float*)d_in[6];   // [1024,H]
    float* out = (float*)d_out;

    float *p_act, *p_y, *p_shact, *p_shared;
    cudaGetSymbolAddress((void**)&p_act,    g_act);
    cudaGetSymbolAddress((void**)&p_y,      g_y);
    cudaGetSymbolAddress((void**)&p_shact,  g_shact);
    cudaGetSymbolAddress((void**)&p_shared, g_shared);

    static cudaStream_t s2 = nullptr;
    static cudaEvent_t  evA = nullptr, evB = nullptr;
    static bool init_done = false;
    if (!init_done) {
        cudaFuncSetAttribute(mgemm<MODE_GATHER, true>,
                             cudaFuncAttributeMaxDynamicSharedMemorySize, SMEM_BYTES);
        cudaFuncSetAttribute(mgemm<MODE_EXPOFF, false>,
                             cudaFuncAttributeMaxDynamicSharedMemorySize, SMEM_BYTES);
        cudaFuncSetAttribute(mgemm<MODE_DIRECT, true>,
                             cudaFuncAttributeMaxDynamicSharedMemorySize, SMEM_BYTES);
        cudaFuncSetAttribute(mgemm<MODE_DIRECT, false>,
                             cudaFuncAttributeMaxDynamicSharedMemorySize, SMEM_BYTES);
        cudaStreamCreateWithFlags(&s2, cudaStreamNonBlocking);
        cudaEventCreateWithFlags(&evA, cudaEventDisableTiming);
        cudaEventCreateWithFlags(&evB, cudaEventDisableTiming);
        init_done = true;
    }

    zero_cnt_kernel<<<1, 64>>>();
    cudaEventRecord(evA, 0);
    cudaStreamWaitEvent(s2, evA, 0);

    // ---- shared experts on side stream (independent of routing) ----
    mgemm<MODE_DIRECT, true><<<dim3(1024 / 128, T_TOK / 128, 1), 256, SMEM_BYTES, s2>>>(
        x, ws_gate_up, p_shact,
        HDIM, HDIM, 2048, 1024, /*pair*/ 1024,
        0LL, 0LL, 0LL, T_TOK);
    mgemm<MODE_DIRECT, false><<<dim3(HDIM / 256, T_TOK / 128, 1), 256, SMEM_BYTES, s2>>>(
        p_shact, ws_down, p_shared,
        1024, 1024, HDIM, HDIM, /*pair*/ 0,
        0LL, 0LL, 0LL, T_TOK);
    cudaEventRecord(evB, s2);

    // ---- routed path on default stream ----
    router_kernel<<<T_TOK / 8, 256>>>(x, gate_w, e_bias);

    mgemm<MODE_GATHER, true><<<dim3(IDIM / 128, CAP / 128, NEXP), 256, SMEM_BYTES>>>(
        x, w_gate_up, p_act,
        HDIM, HDIM, 2 * IDIM, IDIM, /*pair*/ IDIM,
        0LL, (long long)HDIM * 2 * IDIM, (long long)CAP * IDIM, 0);

    mgemm<MODE_EXPOFF, false><<<dim3(HDIM / 256, CAP / 128, NEXP), 256, SMEM_BYTES>>>(
        p_act, w_down, p_y,
        IDIM, IDIM, HDIM, HDIM, /*pair*/ 0,
        (long long)CAP * IDIM, (long long)IDIM * HDIM, (long long)CAP * HDIM, 0);

    cudaStreamWaitEvent(0, evB, 0);
    combine_kernel<<<T_TOK, 256>>>(out);
}